// round 2
// baseline (speedup 1.0000x reference)
#include <cuda_runtime.h>
#include <cuda_bf16.h>

#define N_VERTS 262144
#define N_PAIRS 8388608
#define DHAT2   0.0025f
#define EPSF    1e-12f

// 2 MB coords scratch — stays resident in L2 (126 MB) during the gather kernel.
__device__ float2 g_coords[N_VERTS];

// Kernel A: coords = rest + Uu (float4-vectorized over 524288 floats), zero out.
__global__ void build_coords_kernel(const float* __restrict__ Uu,
                                    const float* __restrict__ rest,
                                    float* __restrict__ out) {
    int i = blockIdx.x * blockDim.x + threadIdx.x;
    const int n4 = (N_VERTS * 2) / 4;  // 131072 float4s
    if (i < n4) {
        float4 u = reinterpret_cast<const float4*>(Uu)[i];
        float4 r = reinterpret_cast<const float4*>(rest)[i];
        float4 c;
        c.x = u.x + r.x;
        c.y = u.y + r.y;
        c.z = u.z + r.z;
        c.w = u.w + r.w;
        reinterpret_cast<float4*>(g_coords)[i] = c;
    }
    if (i == 0) *out = 0.0f;  // d_out is poisoned; kernel B accumulates into it
}

__device__ __forceinline__ float barrier_term(float2 p, float2 a, float2 b) {
    float abx = b.x - a.x, aby = b.y - a.y;
    float apx = p.x - a.x, apy = p.y - a.y;
    float denom = abx * abx + aby * aby;
    float t = (apx * abx + apy * aby) / fmaxf(denom, EPSF);
    t = fminf(fmaxf(t, 0.0f), 1.0f);
    float dx = apx - t * abx;
    float dy = apy - t * aby;
    float d2 = dx * dx + dy * dy;
    if (d2 < DHAT2) {
        float d2s = fmaxf(d2, EPSF);
        float g = d2s - DHAT2;
        return -(g * g) * __logf(d2s * (1.0f / DHAT2));
    }
    return 0.0f;
}

// Kernel B: 4 pairs per thread via int4 index loads; gather coords (L2-resident);
// warp-shuffle + smem block reduction; one atomicAdd per block.
__global__ void __launch_bounds__(256)
barrier_energy_kernel(const int4* __restrict__ pv,
                      const int4* __restrict__ pe0,
                      const int4* __restrict__ pe1,
                      float* __restrict__ out) {
    const int i = blockIdx.x * blockDim.x + threadIdx.x;  // one int4 (=4 pairs)
    float acc = 0.0f;

    if (i < N_PAIRS / 4) {
        int4 v  = pv[i];
        int4 e0 = pe0[i];
        int4 e1 = pe1[i];

        acc += barrier_term(__ldg(&g_coords[v.x]), __ldg(&g_coords[e0.x]), __ldg(&g_coords[e1.x]));
        acc += barrier_term(__ldg(&g_coords[v.y]), __ldg(&g_coords[e0.y]), __ldg(&g_coords[e1.y]));
        acc += barrier_term(__ldg(&g_coords[v.z]), __ldg(&g_coords[e0.z]), __ldg(&g_coords[e1.z]));
        acc += barrier_term(__ldg(&g_coords[v.w]), __ldg(&g_coords[e0.w]), __ldg(&g_coords[e1.w]));
    }

    // warp reduction
    #pragma unroll
    for (int off = 16; off > 0; off >>= 1)
        acc += __shfl_down_sync(0xFFFFFFFFu, acc, off);

    __shared__ float warp_sums[8];  // 256 threads / 32
    int lane = threadIdx.x & 31;
    int wid  = threadIdx.x >> 5;
    if (lane == 0) warp_sums[wid] = acc;
    __syncthreads();

    if (wid == 0) {
        float s = (lane < 8) ? warp_sums[lane] : 0.0f;
        #pragma unroll
        for (int off = 4; off > 0; off >>= 1)
            s += __shfl_down_sync(0xFFFFFFFFu, s, off);
        if (lane == 0) atomicAdd(out, s);
    }
}

extern "C" void kernel_launch(void* const* d_in, const int* in_sizes, int n_in,
                              void* d_out, int out_size) {
    const float* Uu   = (const float*)d_in[0];
    const float* rest = (const float*)d_in[1];
    const int*   pv   = (const int*)d_in[2];
    const int*   pe0  = (const int*)d_in[3];
    const int*   pe1  = (const int*)d_in[4];
    float* out = (float*)d_out;

    {
        const int n4 = (N_VERTS * 2) / 4;  // 131072
        build_coords_kernel<<<(n4 + 255) / 256, 256>>>(Uu, rest, out);
    }
    {
        const int nthreads = N_PAIRS / 4;  // 2097152
        barrier_energy_kernel<<<(nthreads + 255) / 256, 256>>>(
            (const int4*)pv, (const int4*)pe0, (const int4*)pe1, out);
    }
}

// round 3
// speedup vs baseline: 1.0691x; 1.0691x over previous
#include <cuda_runtime.h>
#include <cuda_bf16.h>

#define N_VERTS 262144
#define N_PAIRS 8388608
#define NW      52429        // ceil(N_VERTS / 5) packed words, 6 bits/vertex
#define DHAT2   0.0025f
#define EPSF    1e-12f
#define R2F     0.0625f      // conservative filter threshold (r = 0.25)

// 2 MB coords — stays L2-resident during the gather kernel.
__device__ float2   g_coords[N_VERTS];
// 6-bit quantized coords (3 bits x, 3 bits y), 5 vertices per u32. ~205 KB.
__device__ unsigned g_qtab[NW];

// ---------------------------------------------------------------- kernel A1
__global__ void build_coords_kernel(const float* __restrict__ Uu,
                                    const float* __restrict__ rest,
                                    float* __restrict__ out) {
    int i = blockIdx.x * blockDim.x + threadIdx.x;
    const int n4 = (N_VERTS * 2) / 4;
    if (i < n4) {
        float4 u = reinterpret_cast<const float4*>(Uu)[i];
        float4 r = reinterpret_cast<const float4*>(rest)[i];
        float4 c;
        c.x = u.x + r.x; c.y = u.y + r.y; c.z = u.z + r.z; c.w = u.w + r.w;
        reinterpret_cast<float4*>(g_coords)[i] = c;
    }
    if (i == 0) *out = 0.0f;
}

// ---------------------------------------------------------------- kernel A2
// One thread per packed word: quantize 5 vertices to 3+3 bit grid cells.
__global__ void quantize_kernel() {
    int w = blockIdx.x * blockDim.x + threadIdx.x;
    if (w >= NW) return;
    unsigned packed = 0;
    int base = w * 5;
    #pragma unroll
    for (int k = 0; k < 5; k++) {
        int vi = base + k;
        if (vi < N_VERTS) {
            float2 c = g_coords[vi];
            int qx = min(7, max(0, (int)(c.x * 8.0f)));
            int qy = min(7, max(0, (int)(c.y * 8.0f)));
            packed |= (unsigned)(qx | (qy << 3)) << (6 * k);
        }
    }
    g_qtab[w] = packed;
}

// ---------------------------------------------------------------- helpers
__device__ __forceinline__ float2 dequant(const unsigned* __restrict__ s, int v) {
    unsigned w  = (unsigned)v / 5u;
    unsigned r  = (unsigned)v - w * 5u;
    unsigned q  = (s[w] >> (r * 6u)) & 63u;
    return make_float2((float)(q & 7u) * 0.125f + 0.0625f,
                       (float)(q >> 3) * 0.125f + 0.0625f);
}

// Squared point-segment distance, fast-path division (filter use).
__device__ __forceinline__ float seg_d2_fast(float2 p, float2 a, float2 b) {
    float abx = b.x - a.x, aby = b.y - a.y;
    float apx = p.x - a.x, apy = p.y - a.y;
    float denom = abx * abx + aby * aby;
    float t = __saturatef(__fdividef(apx * abx + apy * aby, fmaxf(denom, EPSF)));
    float dx = apx - t * abx, dy = apy - t * aby;
    return dx * dx + dy * dy;
}

// Exact barrier term (matches reference semantics, precise division).
__device__ __forceinline__ float barrier_term(float2 p, float2 a, float2 b) {
    float abx = b.x - a.x, aby = b.y - a.y;
    float apx = p.x - a.x, apy = p.y - a.y;
    float denom = abx * abx + aby * aby;
    float t = (apx * abx + apy * aby) / fmaxf(denom, EPSF);
    t = __saturatef(t);
    float dx = apx - t * abx, dy = apy - t * aby;
    float d2 = dx * dx + dy * dy;
    if (d2 < DHAT2) {
        float d2s = fmaxf(d2, EPSF);
        float g = d2s - DHAT2;
        return -(g * g) * __logf(d2s * (1.0f / DHAT2));
    }
    return 0.0f;
}

// ---------------------------------------------------------------- kernel B
// Persistent fused kernel: smem quantized filter -> predicated exact gather.
extern __shared__ unsigned s_qtab[];   // NW words (~205 KB dynamic smem)

__global__ void __launch_bounds__(1024, 1)
barrier_energy_fused(const int4* __restrict__ pv,
                     const int4* __restrict__ pe0,
                     const int4* __restrict__ pe1,
                     float* __restrict__ out) {
    // Stage the quantized table (global copy is L2-hot after the first CTA).
    for (int i = threadIdx.x; i < NW; i += blockDim.x)
        s_qtab[i] = g_qtab[i];
    __syncthreads();

    float acc = 0.0f;
    const int nquads = N_PAIRS / 4;
    const int stride = gridDim.x * blockDim.x;

    for (int q = blockIdx.x * blockDim.x + threadIdx.x; q < nquads; q += stride) {
        int4 v  = pv[q];
        int4 e0 = pe0[q];
        int4 e1 = pe1[q];

        #pragma unroll
        for (int k = 0; k < 4; k++) {
            int iv  = (k == 0) ? v.x  : (k == 1) ? v.y  : (k == 2) ? v.z  : v.w;
            int ia  = (k == 0) ? e0.x : (k == 1) ? e0.y : (k == 2) ? e0.z : e0.w;
            int ib  = (k == 0) ? e1.x : (k == 1) ? e1.y : (k == 2) ? e1.z : e1.w;

            float2 qp = dequant(s_qtab, iv);
            float2 qa = dequant(s_qtab, ia);
            float2 qb = dequant(s_qtab, ib);

            if (seg_d2_fast(qp, qa, qb) < R2F) {
                // conservative filter passed -> exact evaluation
                float2 p = __ldg(&g_coords[iv]);
                float2 a = __ldg(&g_coords[ia]);
                float2 b = __ldg(&g_coords[ib]);
                acc += barrier_term(p, a, b);
            }
        }
    }

    // Block reduction (reuse head of s_qtab as float scratch after sync).
    #pragma unroll
    for (int off = 16; off > 0; off >>= 1)
        acc += __shfl_down_sync(0xFFFFFFFFu, acc, off);

    __syncthreads();   // everyone done reading s_qtab
    float* warp_sums = reinterpret_cast<float*>(s_qtab);
    int lane = threadIdx.x & 31;
    int wid  = threadIdx.x >> 5;
    if (lane == 0) warp_sums[wid] = acc;
    __syncthreads();

    if (wid == 0) {
        int nw = blockDim.x >> 5;   // 32
        float s = (lane < nw) ? warp_sums[lane] : 0.0f;
        #pragma unroll
        for (int off = 16; off > 0; off >>= 1)
            s += __shfl_down_sync(0xFFFFFFFFu, s, off);
        if (lane == 0) atomicAdd(out, s);
    }
}

// ---------------------------------------------------------------- launch
extern "C" void kernel_launch(void* const* d_in, const int* in_sizes, int n_in,
                              void* d_out, int out_size) {
    const float* Uu   = (const float*)d_in[0];
    const float* rest = (const float*)d_in[1];
    const int*   pv   = (const int*)d_in[2];
    const int*   pe0  = (const int*)d_in[3];
    const int*   pe1  = (const int*)d_in[4];
    float* out = (float*)d_out;

    {
        const int n4 = (N_VERTS * 2) / 4;
        build_coords_kernel<<<(n4 + 255) / 256, 256>>>(Uu, rest, out);
    }
    quantize_kernel<<<(NW + 255) / 256, 256>>>();

    const size_t smem_bytes = (size_t)NW * sizeof(unsigned);   // ~205 KB
    static bool attr_set = false;
    // Idempotent attribute set (host-side, not a device allocation).
    cudaFuncSetAttribute(barrier_energy_fused,
                         cudaFuncAttributeMaxDynamicSharedMemorySize,
                         (int)smem_bytes);
    (void)attr_set;

    int nsm = 148;
    cudaDeviceGetAttribute(&nsm, cudaDevAttrMultiProcessorCount, 0);

    barrier_energy_fused<<<nsm, 1024, smem_bytes>>>(
        (const int4*)pv, (const int4*)pe0, (const int4*)pe1, out);
}